// round 10
// baseline (speedup 1.0000x reference)
#include <cuda_runtime.h>

typedef unsigned long long u64;

#define Bsz 256
#define Lsz 500
#define Hsz 512
#define Isz 35
#define OUTsz 35

// Scratch: encoder writes c[l][b][h]; scan converts IN-PLACE to
// h[l][b][h] = relu(b_enc + exclusive prefix); decoder reads it. 262 MB.
__device__ float g_c[(size_t)Lsz * Bsz * Hsz];

// ---- packed f32x2 helpers ----
__device__ __forceinline__ u64 fma2(u64 a, u64 b, u64 c) {
    u64 d;
    asm("fma.rn.f32x2 %0, %1, %2, %3;" : "=l"(d) : "l"(a), "l"(b), "l"(c));
    return d;
}
__device__ __forceinline__ u64 pack2(float x, float y) {
    u64 r;
    asm("mov.b64 %0, {%1, %2};" : "=l"(r) : "f"(x), "f"(y));
    return r;
}
__device__ __forceinline__ void unpack2(u64 v, float& x, float& y) {
    asm("mov.b64 {%0, %1}, %2;" : "=f"(x), "=f"(y) : "l"(v));
}
__device__ __forceinline__ unsigned smem_u32(const void* p) {
    return (unsigned)__cvta_generic_to_shared(p);
}
__device__ __forceinline__ void cp_async16(unsigned dst, const void* src) {
    asm volatile("cp.async.cg.shared.global [%0], [%1], 16;" ::
                 "r"(dst), "l"(src));
}
__device__ __forceinline__ void cp_commit() {
    asm volatile("cp.async.commit_group;");
}
template <int N>
__device__ __forceinline__ void cp_wait() {
    asm volatile("cp.async.wait_group %0;" :: "n"(N));
}

// ============================================================
// Kernel 1: encoder (R5 kernel, b_off-parameterized).
// f32x2 lanes = i-pairs; W for 2 h columns in 72 regs, reused over 32 b;
// x broadcast via LDS.128. grid (bq=4, l=500) per half, block 256.
// ============================================================
__global__ void __launch_bounds__(256, 2) enc_kernel(
    const float* __restrict__ inputs,  // [B, L, 3]
    const float* __restrict__ z,       // [B, L, 32]
    const float* __restrict__ W,       // [L, 35, 512]
    const int b_off)
{
    const int bq = blockIdx.x;   // b tile (32 b) within half
    const int l  = blockIdx.y;
    const int t  = threadIdx.x;

    __shared__ __align__(16) float xsf[32][36];   // i padded to 36, x[35]=0

    for (int idx = t; idx < 32 * 36; idx += 256) {
        int bl = idx / 36, i = idx - bl * 36;
        int b = b_off + bq * 32 + bl;
        float v = 0.f;
        if (i < 3)       v = inputs[(b * Lsz + l) * 3 + i];
        else if (i < 35) v = z[(b * Lsz + l) * 32 + (i - 3)];
        xsf[bl][i] = v;
    }

    u64 w0[18], w1[18];
    const float* Wl = W + (size_t)l * Isz * Hsz;
#pragma unroll
    for (int q = 0; q < 17; q++) {
        w0[q] = pack2(Wl[(2 * q) * Hsz + t],       Wl[(2 * q + 1) * Hsz + t]);
        w1[q] = pack2(Wl[(2 * q) * Hsz + t + 256], Wl[(2 * q + 1) * Hsz + t + 256]);
    }
    w0[17] = pack2(Wl[34 * Hsz + t], 0.f);
    w1[17] = pack2(Wl[34 * Hsz + t + 256], 0.f);
    __syncthreads();

    float* crow = &g_c[((size_t)l * Bsz + b_off + bq * 32) * Hsz];
    for (int bl = 0; bl < 32; bl++) {
        u64 a0 = 0ULL, b0 = 0ULL, a1 = 0ULL, b1 = 0ULL;
#pragma unroll
        for (int Q = 0; Q < 9; Q++) {
            ulonglong2 xv = *reinterpret_cast<const ulonglong2*>(&xsf[bl][4 * Q]);
            a0 = fma2(xv.x, w0[2 * Q],     a0);
            b0 = fma2(xv.y, w0[2 * Q + 1], b0);
            a1 = fma2(xv.x, w1[2 * Q],     a1);
            b1 = fma2(xv.y, w1[2 * Q + 1], b1);
        }
        float p, q, r, s;
        unpack2(a0, p, q); unpack2(b0, r, s);
        crow[(size_t)bl * Hsz + t] = (p + q) + (r + s);
        unpack2(a1, p, q); unpack2(b1, r, s);
        crow[(size_t)bl * Hsz + t + 256] = (p + q) + (r + s);
    }
}

// ============================================================
// Kernel 2: half-scan, SCALAR columns to keep 65536 threads per half
// (MLP is the binding constraint for this streaming pass).
// In-place exclusive scan over l + b_enc + ReLU for b in [b_off, b_off+128).
// ============================================================
__global__ void __launch_bounds__(128) scan_kernel(
    const float* __restrict__ benc,    // [1, 512]
    const int b_off)
{
    const int g = blockIdx.x * 128 + threadIdx.x;   // 0..65535
    const int b = b_off + (g >> 9);
    const int h = g & 511;

    const float be = benc[h];
    float* p = g_c + (size_t)b * Hsz + h;
    const size_t stride = (size_t)Bsz * Hsz;

    float a = 0.f;
#pragma unroll 4
    for (int l = 0; l < Lsz; l++) {
        float v = p[l * stride];
        p[l * stride] = fmaxf(a + be, 0.f);
        a += v;
    }
}

// ============================================================
// Kernel 3: decoder (R8 kernel, b_off-parameterized; 500 blocks = 1 wave).
// 4b x 10o per thread (40 fma2 : 9 LDS per k-pair); k-pair lanes;
// h double-buffered via cp.async; V register-prefetched.
// grid (l=500), block 128.
// ============================================================
__global__ void __launch_bounds__(128, 4) dec_kernel(
    const float* __restrict__ Vmu,   // [L, 512, 15]
    const float* __restrict__ bmu,   // [L, 1, 15]
    const float* __restrict__ Vsig,  // [L, 512, 15]
    const float* __restrict__ bsig,  // [L, 1, 15]
    const float* __restrict__ Vpi,   // [L, 512, 5]
    const float* __restrict__ bpi,   // [L, 1, 5]
    float* __restrict__ out,         // [B, L, 35]
    const int b_off)
{
    const int l  = blockIdx.x;
    const int t  = threadIdx.x;
    const int ot = t & 3;            // 10 consecutive o
    const int bt = t >> 2;           // 0..31; b = b_off + bt + 32*ii

    __shared__ __align__(16) u64 hsb[2][128][18];  // k-pairs raw, row=144B
    __shared__ __align__(16) u64 vsb[2][16][40];   // V k-pair packs, o padded

    const float* vptr[5];
    int vkkp[5], vo[5], vrow[5];
    bool vp[5];
#pragma unroll
    for (int j = 0; j < 5; j++) {
        int e = t + 128 * j;
        vp[j] = (e < 16 * 35);
        int kk = vp[j] ? e / 35 : 0;
        int o  = vp[j] ? e - kk * 35 : 0;
        vkkp[j] = kk; vo[j] = o;
        if (o < 15)      { vptr[j] = Vmu  + ((size_t)l * Hsz + 2 * kk) * 15 + o;        vrow[j] = 15; }
        else if (o < 30) { vptr[j] = Vsig + ((size_t)l * Hsz + 2 * kk) * 15 + (o - 15); vrow[j] = 15; }
        else             { vptr[j] = Vpi  + ((size_t)l * Hsz + 2 * kk) * 5  + (o - 30); vrow[j] = 5;  }
    }
    u64 vheld[5];
#define LDV()                                                        \
    do {                                                             \
        _Pragma("unroll")                                            \
        for (int j = 0; j < 5; j++)                                  \
            if (vp[j]) {                                             \
                vheld[j] = pack2(vptr[j][0], vptr[j][vrow[j]]);      \
                vptr[j] += 32 * vrow[j];                             \
            }                                                        \
    } while (0)
#define STV(bf)                                                      \
    do {                                                             \
        _Pragma("unroll")                                            \
        for (int j = 0; j < 5; j++)                                  \
            if (vp[j]) vsb[bf][vkkp[j]][vo[j]] = vheld[j];           \
    } while (0)

    const float* hbase = &g_c[((size_t)l * Bsz + b_off) * Hsz];
#define CPH(tile, bf)                                                     \
    do {                                                                  \
        const float* src_ = hbase + (tile) * 32;                         \
        _Pragma("unroll")                                                 \
        for (int n = 0; n < 8; n++) {                                     \
            int idx_ = t + 128 * n;                                       \
            int row_ = idx_ >> 3, ch_ = idx_ & 7;                         \
            cp_async16(smem_u32(&hsb[bf][row_][ch_ * 2]),                 \
                       src_ + (size_t)row_ * Hsz + ch_ * 4);              \
        }                                                                 \
        cp_commit();                                                      \
    } while (0)

    float bias[10];
#pragma unroll
    for (int j = 0; j < 10; j++) {
        int o = 10 * ot + j;
        bias[j] = (o < 15) ? bmu[l * 15 + o]
                : (o < 30) ? bsig[l * 15 + (o - 15)]
                : (o < 35) ? bpi[l * 5 + (o - 30)] : 0.f;
    }

    LDV();              // V(0)
    STV(0);
    LDV();              // V(1) held
    CPH(0, 0);
    CPH(1, 1);

    u64 acc[4][10];
#pragma unroll
    for (int ii = 0; ii < 4; ii++)
#pragma unroll
        for (int j = 0; j < 10; j++) acc[ii][j] = 0ULL;

    for (int tl = 0; tl < 16; tl++) {
        if (tl < 15) cp_wait<1>(); else cp_wait<0>();
        __syncthreads();
        if (tl < 15) STV((tl + 1) & 1);
        if (tl < 14) LDV();          // V(tl+2)

        const int buf = tl & 1;
#pragma unroll
        for (int kk = 0; kk < 16; kk++) {
            u64 hv[4];
#pragma unroll
            for (int ii = 0; ii < 4; ii++) hv[ii] = hsb[buf][bt + 32 * ii][kk];
            u64 vv[10];
#pragma unroll
            for (int jq = 0; jq < 5; jq++) {
                ulonglong2 q2 = *reinterpret_cast<const ulonglong2*>(
                    &vsb[buf][kk][10 * ot + 2 * jq]);
                vv[2 * jq] = q2.x; vv[2 * jq + 1] = q2.y;
            }
#pragma unroll
            for (int ii = 0; ii < 4; ii++)
#pragma unroll
                for (int j = 0; j < 10; j++)
                    acc[ii][j] = fma2(hv[ii], vv[j], acc[ii][j]);
        }
        __syncthreads();
        if (tl < 14) CPH(tl + 2, buf);
    }

#pragma unroll
    for (int ii = 0; ii < 4; ii++) {
        int b = b_off + bt + 32 * ii;
        float* op = &out[((size_t)b * Lsz + l) * OUTsz];
#pragma unroll
        for (int j = 0; j < 10; j++) {
            int o = 10 * ot + j;
            if (o < OUTsz) {
                float lo, hi;
                unpack2(acc[ii][j], lo, hi);
                op[o] = lo + hi + bias[j];
            }
        }
    }
#undef LDV
#undef STV
#undef CPH
}

extern "C" void kernel_launch(void* const* d_in, const int* in_sizes, int n_in,
                              void* d_out, int out_size) {
    (void)in_sizes; (void)n_in; (void)out_size;
    const float* inputs = (const float*)d_in[0];
    const float* z      = (const float*)d_in[1];
    const float* W_enc  = (const float*)d_in[2];
    const float* b_enc  = (const float*)d_in[3];
    const float* V_mu   = (const float*)d_in[4];
    const float* b_mu   = (const float*)d_in[5];
    const float* V_sig  = (const float*)d_in[6];
    const float* b_sig  = (const float*)d_in[7];
    const float* V_pi   = (const float*)d_in[8];
    const float* b_pi   = (const float*)d_in[9];
    float* out = (float*)d_out;

    // One-time host resources (created on the uncaptured correctness call;
    // the launched GPU work is identical on every call).
    static cudaStream_t s1 = nullptr;
    static cudaEvent_t eFork = nullptr, eJoin = nullptr;
    if (s1 == nullptr) {
        cudaStreamCreateWithFlags(&s1, cudaStreamNonBlocking);
        cudaEventCreateWithFlags(&eFork, cudaEventDisableTiming);
        cudaEventCreateWithFlags(&eJoin, cudaEventDisableTiming);
    }

    // Chain A: b[0,128) on the calling (capture-origin) stream.
    // Chain B: b[128,256) on s1, forked after encA so that DRAM-heavy
    // scans overlap fma-heavy enc/dec stages of the other chain.
    enc_kernel<<<dim3(4, Lsz), 256>>>(inputs, z, W_enc, 0);
    cudaEventRecord(eFork, 0);
    cudaStreamWaitEvent(s1, eFork, 0);

    enc_kernel<<<dim3(4, Lsz), 256, 0, s1>>>(inputs, z, W_enc, 128);

    scan_kernel<<<512, 128>>>(b_enc, 0);
    dec_kernel<<<Lsz, 128>>>(V_mu, b_mu, V_sig, b_sig, V_pi, b_pi, out, 0);

    scan_kernel<<<512, 128, 0, s1>>>(b_enc, 128);
    dec_kernel<<<Lsz, 128, 0, s1>>>(V_mu, b_mu, V_sig, b_sig, V_pi, b_pi, out, 128);

    cudaEventRecord(eJoin, s1);
    cudaStreamWaitEvent(0, eJoin, 0);
}

// round 11
// speedup vs baseline: 1.0951x; 1.0951x over previous
#include <cuda_runtime.h>

typedef unsigned long long u64;

#define Bsz 256
#define Lsz 500
#define Hsz 512
#define Isz 35
#define OUTsz 35

// Scratch: encoder writes c[l][b][h]; scan converts IN-PLACE to
// h[l][b][h] = relu(b_enc + exclusive prefix); decoder reads it. 262 MB.
__device__ float g_c[(size_t)Lsz * Bsz * Hsz];

// ---- packed f32x2 helpers ----
__device__ __forceinline__ u64 fma2(u64 a, u64 b, u64 c) {
    u64 d;
    asm("fma.rn.f32x2 %0, %1, %2, %3;" : "=l"(d) : "l"(a), "l"(b), "l"(c));
    return d;
}
__device__ __forceinline__ u64 pack2(float x, float y) {
    u64 r;
    asm("mov.b64 %0, {%1, %2};" : "=l"(r) : "f"(x), "f"(y));
    return r;
}
__device__ __forceinline__ void unpack2(u64 v, float& x, float& y) {
    asm("mov.b64 {%0, %1}, %2;" : "=f"(x), "=f"(y) : "l"(v));
}
__device__ __forceinline__ unsigned smem_u32(const void* p) {
    return (unsigned)__cvta_generic_to_shared(p);
}
__device__ __forceinline__ void cp_async16(unsigned dst, const void* src) {
    asm volatile("cp.async.cg.shared.global [%0], [%1], 16;" ::
                 "r"(dst), "l"(src));
}
__device__ __forceinline__ void cp_commit() {
    asm volatile("cp.async.commit_group;");
}
template <int N>
__device__ __forceinline__ void cp_wait() {
    asm volatile("cp.async.wait_group %0;" :: "n"(N));
}

// ============================================================
// Kernel 1: encoder (R5/R9 exact — 125 us, ~97% of fp32 FMA roofline).
// f32x2 lanes = i-pairs; W for 2 h columns in 72 regs, reused over 32 b;
// x broadcast via LDS.128. grid (bq=8, l=500), block 256.
// ============================================================
__global__ void __launch_bounds__(256, 2) enc_kernel(
    const float* __restrict__ inputs,  // [B, L, 3]
    const float* __restrict__ z,       // [B, L, 32]
    const float* __restrict__ W)       // [L, 35, 512]
{
    const int bq = blockIdx.x;   // b tile (32 b)
    const int l  = blockIdx.y;
    const int t  = threadIdx.x;

    __shared__ __align__(16) float xsf[32][36];   // i padded to 36, x[35]=0

    for (int idx = t; idx < 32 * 36; idx += 256) {
        int bl = idx / 36, i = idx - bl * 36;
        int b = bq * 32 + bl;
        float v = 0.f;
        if (i < 3)       v = inputs[(b * Lsz + l) * 3 + i];
        else if (i < 35) v = z[(b * Lsz + l) * 32 + (i - 3)];
        xsf[bl][i] = v;
    }

    u64 w0[18], w1[18];
    const float* Wl = W + (size_t)l * Isz * Hsz;
#pragma unroll
    for (int q = 0; q < 17; q++) {
        w0[q] = pack2(Wl[(2 * q) * Hsz + t],       Wl[(2 * q + 1) * Hsz + t]);
        w1[q] = pack2(Wl[(2 * q) * Hsz + t + 256], Wl[(2 * q + 1) * Hsz + t + 256]);
    }
    w0[17] = pack2(Wl[34 * Hsz + t], 0.f);
    w1[17] = pack2(Wl[34 * Hsz + t + 256], 0.f);
    __syncthreads();

    float* crow = &g_c[((size_t)l * Bsz + bq * 32) * Hsz];
    for (int bl = 0; bl < 32; bl++) {
        u64 a0 = 0ULL, b0 = 0ULL, a1 = 0ULL, b1 = 0ULL;
#pragma unroll
        for (int Q = 0; Q < 9; Q++) {
            ulonglong2 xv = *reinterpret_cast<const ulonglong2*>(&xsf[bl][4 * Q]);
            a0 = fma2(xv.x, w0[2 * Q],     a0);
            b0 = fma2(xv.y, w0[2 * Q + 1], b0);
            a1 = fma2(xv.x, w1[2 * Q],     a1);
            b1 = fma2(xv.y, w1[2 * Q + 1], b1);
        }
        float p, q, r, s;
        unpack2(a0, p, q); unpack2(b0, r, s);
        crow[(size_t)bl * Hsz + t] = (p + q) + (r + s);
        unpack2(a1, p, q); unpack2(b1, r, s);
        crow[(size_t)bl * Hsz + t + 256] = (p + q) + (r + s);
    }
}

// ============================================================
// Kernel 2: scan (R9 exact — float2, 65536 threads, 512 blocks).
// In-place exclusive scan over l + b_enc + ReLU.
// ============================================================
__global__ void __launch_bounds__(128) scan_kernel(
    const float* __restrict__ benc)    // [1, 512]
{
    const int g = blockIdx.x * 128 + threadIdx.x;   // 0..65535
    const int b = g >> 8;
    const int hp = g & 255;

    float2 be = *reinterpret_cast<const float2*>(&benc[2 * hp]);
    float2* p = reinterpret_cast<float2*>(g_c) + ((size_t)b * Hsz) / 2 + hp;
    const size_t stride = (size_t)Bsz * Hsz / 2;

    float ax = 0.f, ay = 0.f;
#pragma unroll 4
    for (int l = 0; l < Lsz; l++) {
        float2 v = p[l * stride];
        float2 o;
        o.x = fmaxf(ax + be.x, 0.f);
        o.y = fmaxf(ay + be.y, 0.f);
        p[l * stride] = o;
        ax += v.x; ay += v.y;
    }
}

// ============================================================
// Kernel 3: decoder — R9 structure, o-padding cut from 40->36 slots.
// 4b x 9o per thread (36 fma2 : 13 LDS per k-pair); k-pair lanes;
// h double-buffered via cp.async; V register-prefetched.
// ot covers o in [9*ot, 9*ot+9); slot o=35 is a discard column.
// grid (bq=2, l=500), block 128.
// ============================================================
__global__ void __launch_bounds__(128, 4) dec_kernel(
    const float* __restrict__ Vmu,   // [L, 512, 15]
    const float* __restrict__ bmu,   // [L, 1, 15]
    const float* __restrict__ Vsig,  // [L, 512, 15]
    const float* __restrict__ bsig,  // [L, 1, 15]
    const float* __restrict__ Vpi,   // [L, 512, 5]
    const float* __restrict__ bpi,   // [L, 1, 5]
    float* __restrict__ out)         // [B, L, 35]
{
    const int bq = blockIdx.x;       // b tile (128 b)
    const int l  = blockIdx.y;
    const int t  = threadIdx.x;
    const int ot = t & 3;            // 9 consecutive o (last group: 8 real)
    const int bt = t >> 2;           // 0..31; b = bt + 32*ii, ii 0..3

    __shared__ __align__(16) u64 hsb[2][128][18];  // k-pairs raw, row=144B
    __shared__ __align__(16) u64 vsb[2][16][36];   // V k-pair packs, col 35 = discard

    // ---- V prefetch bookkeeping: 560 entries, 5 per thread ----
    const float* vptr[5];
    int vkkp[5], vo[5], vrow[5];
    bool vp[5];
#pragma unroll
    for (int j = 0; j < 5; j++) {
        int e = t + 128 * j;
        vp[j] = (e < 16 * 35);
        int kk = vp[j] ? e / 35 : 0;
        int o  = vp[j] ? e - kk * 35 : 0;
        vkkp[j] = kk; vo[j] = o;
        if (o < 15)      { vptr[j] = Vmu  + ((size_t)l * Hsz + 2 * kk) * 15 + o;        vrow[j] = 15; }
        else if (o < 30) { vptr[j] = Vsig + ((size_t)l * Hsz + 2 * kk) * 15 + (o - 15); vrow[j] = 15; }
        else             { vptr[j] = Vpi  + ((size_t)l * Hsz + 2 * kk) * 5  + (o - 30); vrow[j] = 5;  }
    }
    u64 vheld[5];
#define LDV()                                                        \
    do {                                                             \
        _Pragma("unroll")                                            \
        for (int j = 0; j < 5; j++)                                  \
            if (vp[j]) {                                             \
                vheld[j] = pack2(vptr[j][0], vptr[j][vrow[j]]);      \
                vptr[j] += 32 * vrow[j];                             \
            }                                                        \
    } while (0)
#define STV(bf)                                                      \
    do {                                                             \
        _Pragma("unroll")                                            \
        for (int j = 0; j < 5; j++)                                  \
            if (vp[j]) vsb[bf][vkkp[j]][vo[j]] = vheld[j];           \
    } while (0)

    const float* hbase = &g_c[((size_t)l * Bsz + bq * 128) * Hsz];
#define CPH(tile, bf)                                                     \
    do {                                                                  \
        const float* src_ = hbase + (tile) * 32;                         \
        _Pragma("unroll")                                                 \
        for (int n = 0; n < 8; n++) {                                     \
            int idx_ = t + 128 * n;                                       \
            int row_ = idx_ >> 3, ch_ = idx_ & 7;                         \
            cp_async16(smem_u32(&hsb[bf][row_][ch_ * 2]),                 \
                       src_ + (size_t)row_ * Hsz + ch_ * 4);              \
        }                                                                 \
        cp_commit();                                                      \
    } while (0)

    // bias for this thread's 9 o columns (col 35 discard -> 0)
    float bias[9];
#pragma unroll
    for (int j = 0; j < 9; j++) {
        int o = 9 * ot + j;
        bias[j] = (o < 15) ? bmu[l * 15 + o]
                : (o < 30) ? bsig[l * 15 + (o - 15)]
                : (o < 35) ? bpi[l * 5 + (o - 30)] : 0.f;
    }

    // ---- prolog ----
    LDV();              // V(0)
    STV(0);
    LDV();              // V(1) held
    CPH(0, 0);
    CPH(1, 1);

    u64 acc[4][9];
#pragma unroll
    for (int ii = 0; ii < 4; ii++)
#pragma unroll
        for (int j = 0; j < 9; j++) acc[ii][j] = 0ULL;

    for (int tl = 0; tl < 16; tl++) {
        if (tl < 15) cp_wait<1>(); else cp_wait<0>();
        __syncthreads();
        if (tl < 15) STV((tl + 1) & 1);
        if (tl < 14) LDV();          // V(tl+2)

        const int buf = tl & 1;
#pragma unroll
        for (int kk = 0; kk < 16; kk++) {
            u64 hv[4];
#pragma unroll
            for (int ii = 0; ii < 4; ii++) hv[ii] = hsb[buf][bt + 32 * ii][kk];
            u64 vv[9];
#pragma unroll
            for (int j = 0; j < 9; j++)
                vv[j] = vsb[buf][kk][9 * ot + j];   // col 35 = garbage, discarded
#pragma unroll
            for (int ii = 0; ii < 4; ii++)
#pragma unroll
                for (int j = 0; j < 9; j++)
                    acc[ii][j] = fma2(hv[ii], vv[j], acc[ii][j]);
        }
        __syncthreads();
        if (tl < 14) CPH(tl + 2, buf);
    }

    // epilogue: horizontal add over k-pair lanes + bias
#pragma unroll
    for (int ii = 0; ii < 4; ii++) {
        int b = bq * 128 + bt + 32 * ii;
        float* op = &out[((size_t)b * Lsz + l) * OUTsz];
#pragma unroll
        for (int j = 0; j < 9; j++) {
            int o = 9 * ot + j;
            if (o < OUTsz) {
                float lo, hi;
                unpack2(acc[ii][j], lo, hi);
                op[o] = lo + hi + bias[j];
            }
        }
    }
#undef LDV
#undef STV
#undef CPH
}

extern "C" void kernel_launch(void* const* d_in, const int* in_sizes, int n_in,
                              void* d_out, int out_size) {
    (void)in_sizes; (void)n_in; (void)out_size;
    const float* inputs = (const float*)d_in[0];
    const float* z      = (const float*)d_in[1];
    const float* W_enc  = (const float*)d_in[2];
    const float* b_enc  = (const float*)d_in[3];
    const float* V_mu   = (const float*)d_in[4];
    const float* b_mu   = (const float*)d_in[5];
    const float* V_sig  = (const float*)d_in[6];
    const float* b_sig  = (const float*)d_in[7];
    const float* V_pi   = (const float*)d_in[8];
    const float* b_pi   = (const float*)d_in[9];
    float* out = (float*)d_out;

    enc_kernel<<<dim3(8, Lsz), 256>>>(inputs, z, W_enc);
    scan_kernel<<<(Bsz * Hsz / 2) / 128, 128>>>(b_enc);
    dec_kernel<<<dim3(2, Lsz), 128>>>(V_mu, b_mu, V_sig, b_sig, V_pi, b_pi, out);
}

// round 13
// speedup vs baseline: 1.1030x; 1.0072x over previous
#include <cuda_runtime.h>
#include <cuda_bf16.h>
#include <cstdint>

typedef unsigned long long u64;

#define Bsz 256
#define Lsz 500
#define Hsz 512
#define Isz 35
#define OUTsz 35

// enc -> g_c (fp32 c values); scan reads g_c, writes bf16-split h packs.
__device__ float    g_c  [(size_t)Lsz * Bsz * Hsz];
__device__ uint32_t g_hhi[(size_t)Lsz * Bsz * (Hsz / 2)];  // bf16x2 k-pairs
__device__ uint32_t g_hlo[(size_t)Lsz * Bsz * (Hsz / 2)];

// ---- packed f32x2 helpers (enc) ----
__device__ __forceinline__ u64 fma2(u64 a, u64 b, u64 c) {
    u64 d;
    asm("fma.rn.f32x2 %0, %1, %2, %3;" : "=l"(d) : "l"(a), "l"(b), "l"(c));
    return d;
}
__device__ __forceinline__ u64 pack2(float x, float y) {
    u64 r;
    asm("mov.b64 %0, {%1, %2};" : "=l"(r) : "f"(x), "f"(y));
    return r;
}
__device__ __forceinline__ void unpack2(u64 v, float& x, float& y) {
    asm("mov.b64 {%0, %1}, %2;" : "=f"(x), "=f"(y) : "l"(v));
}
__device__ __forceinline__ unsigned smem_u32(const void* p) {
    return (unsigned)__cvta_generic_to_shared(p);
}
__device__ __forceinline__ void cp_async16(unsigned dst, const void* src) {
    asm volatile("cp.async.cg.shared.global [%0], [%1], 16;" ::
                 "r"(dst), "l"(src));
}
__device__ __forceinline__ void cp_commit() {
    asm volatile("cp.async.commit_group;");
}
template <int N>
__device__ __forceinline__ void cp_wait() {
    asm volatile("cp.async.wait_group %0;" :: "n"(N));
}

// split two fp32 into bf16x2 hi-pack + lo-pack (x -> low 16 bits)
__device__ __forceinline__ void bsplit2(float x, float y,
                                        uint32_t& hi, uint32_t& lo) {
    __nv_bfloat162 h, l2;
    h.x = __float2bfloat16(x);
    h.y = __float2bfloat16(y);
    l2.x = __float2bfloat16(x - __bfloat162float(h.x));
    l2.y = __float2bfloat16(y - __bfloat162float(h.y));
    hi = *reinterpret_cast<uint32_t*>(&h);
    lo = *reinterpret_cast<uint32_t*>(&l2);
}

// m16n8k16 bf16 MMA, fp32 accum (plain PTX, sm_80+; no 'a' target needed)
__device__ __forceinline__ void mma_bf16(float d[4], const uint32_t a[4],
                                         const uint32_t b[2]) {
    asm volatile(
        "mma.sync.aligned.m16n8k16.row.col.f32.bf16.bf16.f32 "
        "{%0,%1,%2,%3}, {%4,%5,%6,%7}, {%8,%9}, {%0,%1,%2,%3};"
        : "+f"(d[0]), "+f"(d[1]), "+f"(d[2]), "+f"(d[3])
        : "r"(a[0]), "r"(a[1]), "r"(a[2]), "r"(a[3]),
          "r"(b[0]), "r"(b[1]));
}

// ============================================================
// Kernel 1: encoder (R5/R9/R11 exact — 125 us, ~97% of fp32 roofline).
// ============================================================
__global__ void __launch_bounds__(256, 2) enc_kernel(
    const float* __restrict__ inputs,  // [B, L, 3]
    const float* __restrict__ z,       // [B, L, 32]
    const float* __restrict__ W)       // [L, 35, 512]
{
    const int bq = blockIdx.x;
    const int l  = blockIdx.y;
    const int t  = threadIdx.x;

    __shared__ __align__(16) float xsf[32][36];

    for (int idx = t; idx < 32 * 36; idx += 256) {
        int bl = idx / 36, i = idx - bl * 36;
        int b = bq * 32 + bl;
        float v = 0.f;
        if (i < 3)       v = inputs[(b * Lsz + l) * 3 + i];
        else if (i < 35) v = z[(b * Lsz + l) * 32 + (i - 3)];
        xsf[bl][i] = v;
    }

    u64 w0[18], w1[18];
    const float* Wl = W + (size_t)l * Isz * Hsz;
#pragma unroll
    for (int q = 0; q < 17; q++) {
        w0[q] = pack2(Wl[(2 * q) * Hsz + t],       Wl[(2 * q + 1) * Hsz + t]);
        w1[q] = pack2(Wl[(2 * q) * Hsz + t + 256], Wl[(2 * q + 1) * Hsz + t + 256]);
    }
    w0[17] = pack2(Wl[34 * Hsz + t], 0.f);
    w1[17] = pack2(Wl[34 * Hsz + t + 256], 0.f);
    __syncthreads();

    float* crow = &g_c[((size_t)l * Bsz + bq * 32) * Hsz];
    for (int bl = 0; bl < 32; bl++) {
        u64 a0 = 0ULL, b0 = 0ULL, a1 = 0ULL, b1 = 0ULL;
#pragma unroll
        for (int Q = 0; Q < 9; Q++) {
            ulonglong2 xv = *reinterpret_cast<const ulonglong2*>(&xsf[bl][4 * Q]);
            a0 = fma2(xv.x, w0[2 * Q],     a0);
            b0 = fma2(xv.y, w0[2 * Q + 1], b0);
            a1 = fma2(xv.x, w1[2 * Q],     a1);
            b1 = fma2(xv.y, w1[2 * Q + 1], b1);
        }
        float p, q, r, s;
        unpack2(a0, p, q); unpack2(b0, r, s);
        crow[(size_t)bl * Hsz + t] = (p + q) + (r + s);
        unpack2(a1, p, q); unpack2(b1, r, s);
        crow[(size_t)bl * Hsz + t + 256] = (p + q) + (r + s);
    }
}

// ============================================================
// Kernel 2: scan + bf16-split emit. Exclusive scan over l + b_enc + ReLU;
// writes h as bf16x2 k-pair packs (hi & lo) — the exact A-fragment format
// for m16n8k16. Same traffic volume as before (DRAM-bound).
// ============================================================
__global__ void __launch_bounds__(128) scan_kernel(
    const float* __restrict__ benc)    // [1, 512]
{
    const int g = blockIdx.x * 128 + threadIdx.x;   // 0..65535
    const int b = g >> 8;
    const int hp = g & 255;                          // k-pair index

    float2 be = *reinterpret_cast<const float2*>(&benc[2 * hp]);
    const float2* p = reinterpret_cast<const float2*>(g_c)
                    + (size_t)b * (Hsz / 2) + hp;
    const size_t stride = (size_t)Bsz * Hsz / 2;
    uint32_t* qhi = g_hhi + (size_t)b * 256 + hp;
    uint32_t* qlo = g_hlo + (size_t)b * 256 + hp;
    const size_t ostride = (size_t)Bsz * 256;

    float ax = 0.f, ay = 0.f;
#pragma unroll 4
    for (int l = 0; l < Lsz; l++) {
        float2 v = p[l * stride];
        float h0 = fmaxf(ax + be.x, 0.f);
        float h1 = fmaxf(ay + be.y, 0.f);
        uint32_t hi, lo;
        bsplit2(h0, h1, hi, lo);
        qhi[l * ostride] = hi;
        qlo[l * ostride] = lo;
        ax += v.x; ay += v.y;
    }
}

// ============================================================
// Kernel 3: HMMA bf16-split decoder.
// D[128b, 40o] = h[128,512] @ V[512,40]^T via 3xBF16, fp32 accum.
// R11 pipeline skeleton: 16 chunks of k=32 (16 k-pairs); h chunks
// double-buffered via cp.async (pre-split in scan); V register-prefetched
// and split at STV. Warp w: rows 32w..32w+31 (2 m16 tiles) x 5 n8 tiles.
// grid (bq=2, l=500), block 128. Dynamic smem 51200 B.
// ============================================================
__global__ void __launch_bounds__(128, 4) dec_mma_kernel(
    const float* __restrict__ Vmu,   // [L, 512, 15]
    const float* __restrict__ bmu,   // [L, 1, 15]
    const float* __restrict__ Vsig,  // [L, 512, 15]
    const float* __restrict__ bsig,  // [L, 1, 15]
    const float* __restrict__ Vpi,   // [L, 512, 5]
    const float* __restrict__ bpi,   // [L, 1, 5]
    float* __restrict__ out)         // [B, L, 35]
{
    const int bq = blockIdx.x;
    const int l  = blockIdx.y;
    const int t  = threadIdx.x;
    const int wid = t >> 5, lane = t & 31;
    const int gr = lane >> 2, t4 = lane & 3;   // fragment row/col ids

    extern __shared__ uint32_t dsm[];
    uint32_t* hs_hi = dsm;            // [2][128][20] (16 kkp + 4 pad)
    uint32_t* hs_lo = dsm + 5120;
    uint32_t* vs_hi = dsm + 10240;    // [2][16][40]
    uint32_t* vs_lo = dsm + 11520;
#define HS(bf, row, c) ((bf) * 2560 + (row) * 20 + (c))
#define VS(bf, kk, o)  ((bf) * 640 + (kk) * 40 + (o))

    // zero V pad cols (o 35..39) once; STV never writes them
    for (int e = t; e < 160; e += 128) {
        int bf = e / 80, r = e - bf * 80;
        vs_hi[VS(bf, r / 5, 35 + r % 5)] = 0;
        vs_lo[VS(bf, r / 5, 35 + r % 5)] = 0;
    }

    // ---- V prefetch bookkeeping: 560 entries/chunk, 5 per thread ----
    const float* vptr[5];
    int vkkp[5], vo[5], vrow[5];
    bool vp[5];
#pragma unroll
    for (int j = 0; j < 5; j++) {
        int e = t + 128 * j;
        vp[j] = (e < 16 * 35);
        int kk = vp[j] ? e / 35 : 0;
        int o  = vp[j] ? e - kk * 35 : 0;
        vkkp[j] = kk; vo[j] = o;
        if (o < 15)      { vptr[j] = Vmu  + ((size_t)l * Hsz + 2 * kk) * 15 + o;        vrow[j] = 15; }
        else if (o < 30) { vptr[j] = Vsig + ((size_t)l * Hsz + 2 * kk) * 15 + (o - 15); vrow[j] = 15; }
        else             { vptr[j] = Vpi  + ((size_t)l * Hsz + 2 * kk) * 5  + (o - 30); vrow[j] = 5;  }
    }
    uint32_t vh[5], vl[5];
#define LDV()                                                          \
    do {                                                               \
        _Pragma("unroll")                                              \
        for (int j = 0; j < 5; j++)                                    \
            if (vp[j]) {                                               \
                bsplit2(vptr[j][0], vptr[j][vrow[j]], vh[j], vl[j]);   \
                vptr[j] += 32 * vrow[j];                               \
            }                                                          \
    } while (0)
#define STV(bf)                                                        \
    do {                                                               \
        _Pragma("unroll")                                              \
        for (int j = 0; j < 5; j++)                                    \
            if (vp[j]) {                                               \
                vs_hi[VS(bf, vkkp[j], vo[j])] = vh[j];                 \
                vs_lo[VS(bf, vkkp[j], vo[j])] = vl[j];                 \
            }                                                          \
    } while (0)

    const uint32_t* hhib = g_hhi + ((size_t)l * Bsz + bq * 128) * 256;
    const uint32_t* hlob = g_hlo + ((size_t)l * Bsz + bq * 128) * 256;
#define CPH(tile, bf)                                                      \
    do {                                                                   \
        _Pragma("unroll")                                                  \
        for (int n = 0; n < 4; n++) {                                      \
            int idx_ = t + 128 * n;                                        \
            int row_ = idx_ >> 2, c_ = idx_ & 3;                           \
            cp_async16(smem_u32(hs_hi + HS(bf, row_, c_ * 4)),             \
                       hhib + (size_t)row_ * 256 + (tile) * 16 + c_ * 4);  \
            cp_async16(smem_u32(hs_lo + HS(bf, row_, c_ * 4)),             \
                       hlob + (size_t)row_ * 256 + (tile) * 16 + c_ * 4);  \
        }                                                                  \
        cp_commit();                                                       \
    } while (0)

    // bias for this thread's columns
    float bias0[5], bias1[5];
#pragma unroll
    for (int nt = 0; nt < 5; nt++) {
#pragma unroll
        for (int s = 0; s < 2; s++) {
            int o = 8 * nt + 2 * t4 + s;
            float bv = (o < 15) ? bmu[l * 15 + o]
                     : (o < 30) ? bsig[l * 15 + (o - 15)]
                     : (o < 35) ? bpi[l * 5 + (o - 30)] : 0.f;
            if (s == 0) bias0[nt] = bv; else bias1[nt] = bv;
        }
    }

    // ---- prolog ----
    LDV();
    STV(0);
    LDV();
    CPH(0, 0);
    CPH(1, 1);

    float d[2][5][4];
#pragma unroll
    for (int mt = 0; mt < 2; mt++)
#pragma unroll
        for (int nt = 0; nt < 5; nt++)
#pragma unroll
            for (int k = 0; k < 4; k++) d[mt][nt][k] = 0.f;

    for (int tl = 0; tl < 16; tl++) {
        if (tl < 15) cp_wait<1>(); else cp_wait<0>();
        __syncthreads();
        if (tl < 15) STV((tl + 1) & 1);
        if (tl < 14) LDV();

        const int buf = tl & 1;
#pragma unroll
        for (int s = 0; s < 2; s++) {          // two k16 steps per chunk
            const int kb = 8 * s;
            uint32_t aH[2][4], aL[2][4];
#pragma unroll
            for (int mt = 0; mt < 2; mt++) {
                int r0 = 32 * wid + 16 * mt + gr;
                aH[mt][0] = hs_hi[HS(buf, r0,     kb + t4)];
                aH[mt][1] = hs_hi[HS(buf, r0 + 8, kb + t4)];
                aH[mt][2] = hs_hi[HS(buf, r0,     kb + 4 + t4)];
                aH[mt][3] = hs_hi[HS(buf, r0 + 8, kb + 4 + t4)];
                aL[mt][0] = hs_lo[HS(buf, r0,     kb + t4)];
                aL[mt][1] = hs_lo[HS(buf, r0 + 8, kb + t4)];
                aL[mt][2] = hs_lo[HS(buf, r0,     kb + 4 + t4)];
                aL[mt][3] = hs_lo[HS(buf, r0 + 8, kb + 4 + t4)];
            }
            uint32_t bH[5][2], bL[5][2];
#pragma unroll
            for (int nt = 0; nt < 5; nt++) {
                int o = 8 * nt + gr;
                bH[nt][0] = vs_hi[VS(buf, kb + t4,     o)];
                bH[nt][1] = vs_hi[VS(buf, kb + 4 + t4, o)];
                bL[nt][0] = vs_lo[VS(buf, kb + t4,     o)];
                bL[nt][1] = vs_lo[VS(buf, kb + 4 + t4, o)];
            }
#pragma unroll
            for (int mt = 0; mt < 2; mt++)
#pragma unroll
                for (int nt = 0; nt < 5; nt++) {
                    mma_bf16(d[mt][nt], aH[mt], bH[nt]);   // hi*hi
                    mma_bf16(d[mt][nt], aH[mt], bL[nt]);   // hi*lo
                    mma_bf16(d[mt][nt], aL[mt], bH[nt]);   // lo*hi
                }
        }
        __syncthreads();
        if (tl < 14) CPH(tl + 2, buf);
    }

    // ---- epilogue: fragment scatter + bias ----
#pragma unroll
    for (int mt = 0; mt < 2; mt++) {
        int b0 = bq * 128 + 32 * wid + 16 * mt + gr;
        float* o0 = out + ((size_t)b0 * Lsz + l) * OUTsz;
        float* o1 = out + ((size_t)(b0 + 8) * Lsz + l) * OUTsz;
#pragma unroll
        for (int nt = 0; nt < 5; nt++) {
            int c0 = 8 * nt + 2 * t4;
            if (c0 < OUTsz) {
                o0[c0] = d[mt][nt][0] + bias0[nt];
                o1[c0] = d[mt][nt][2] + bias0[nt];
            }
            if (c0 + 1 < OUTsz) {
                o0[c0 + 1] = d[mt][nt][1] + bias1[nt];
                o1[c0 + 1] = d[mt][nt][3] + bias1[nt];
            }
        }
    }
#undef LDV
#undef STV
#undef CPH
#undef HS
#undef VS
}

extern "C" void kernel_launch(void* const* d_in, const int* in_sizes, int n_in,
                              void* d_out, int out_size) {
    (void)in_sizes; (void)n_in; (void)out_size;
    const float* inputs = (const float*)d_in[0];
    const float* z      = (const float*)d_in[1];
    const float* W_enc  = (const float*)d_in[2];
    const float* b_enc  = (const float*)d_in[3];
    const float* V_mu   = (const float*)d_in[4];
    const float* b_mu   = (const float*)d_in[5];
    const float* V_sig  = (const float*)d_in[6];
    const float* b_sig  = (const float*)d_in[7];
    const float* V_pi   = (const float*)d_in[8];
    const float* b_pi   = (const float*)d_in[9];
    float* out = (float*)d_out;

    // opt-in to >48KB dynamic smem (attribute set; not an allocation)
    cudaFuncSetAttribute(dec_mma_kernel,
                         cudaFuncAttributeMaxDynamicSharedMemorySize, 51200);

    enc_kernel<<<dim3(8, Lsz), 256>>>(inputs, z, W_enc);
    scan_kernel<<<(Bsz * Hsz / 2) / 128, 128>>>(b_enc);
    dec_mma_kernel<<<dim3(2, Lsz), 128, 51200>>>(V_mu, b_mu, V_sig, b_sig,
                                                 V_pi, b_pi, out);
}

// round 14
// speedup vs baseline: 1.3305x; 1.2062x over previous
#include <cuda_runtime.h>
#include <cstdint>

typedef unsigned long long u64;

#define Bsz 256
#define Lsz 500
#define Hsz 512
#define Isz 35
#define OUTsz 35

// enc writes fp32 c[l][b][h]; scan converts IN-PLACE to tf32-rounded
// h = relu(b_enc + exclusive prefix); dec consumes via tf32 MMA. 262 MB.
__device__ float g_c[(size_t)Lsz * Bsz * Hsz];

// ---- packed f32x2 helpers (enc) ----
__device__ __forceinline__ u64 fma2(u64 a, u64 b, u64 c) {
    u64 d;
    asm("fma.rn.f32x2 %0, %1, %2, %3;" : "=l"(d) : "l"(a), "l"(b), "l"(c));
    return d;
}
__device__ __forceinline__ u64 pack2(float x, float y) {
    u64 r;
    asm("mov.b64 %0, {%1, %2};" : "=l"(r) : "f"(x), "f"(y));
    return r;
}
__device__ __forceinline__ void unpack2(u64 v, float& x, float& y) {
    asm("mov.b64 {%0, %1}, %2;" : "=f"(x), "=f"(y) : "l"(v));
}
__device__ __forceinline__ unsigned smem_u32(const void* p) {
    return (unsigned)__cvta_generic_to_shared(p);
}
__device__ __forceinline__ void cp_async16(unsigned dst, const void* src) {
    asm volatile("cp.async.cg.shared.global [%0], [%1], 16;" ::
                 "r"(dst), "l"(src));
}
__device__ __forceinline__ void cp_commit() {
    asm volatile("cp.async.commit_group;");
}
template <int N>
__device__ __forceinline__ void cp_wait() {
    asm volatile("cp.async.wait_group %0;" :: "n"(N));
}
__device__ __forceinline__ uint32_t to_tf32(float x) {
    uint32_t u;
    asm("cvt.rna.tf32.f32 %0, %1;" : "=r"(u) : "f"(x));
    return u;
}

// m16n8k8 tf32 MMA, fp32 accum (plain PTX, sm_80+)
__device__ __forceinline__ void mma_tf32(float d[4], const uint32_t a[4],
                                         const uint32_t b[2]) {
    asm volatile(
        "mma.sync.aligned.m16n8k8.row.col.f32.tf32.tf32.f32 "
        "{%0,%1,%2,%3}, {%4,%5,%6,%7}, {%8,%9}, {%0,%1,%2,%3};"
        : "+f"(d[0]), "+f"(d[1]), "+f"(d[2]), "+f"(d[3])
        : "r"(a[0]), "r"(a[1]), "r"(a[2]), "r"(a[3]),
          "r"(b[0]), "r"(b[1]));
}

// ============================================================
// Kernel 1: encoder (R5/R9/R11 exact — 125 us).
// ============================================================
__global__ void __launch_bounds__(256, 2) enc_kernel(
    const float* __restrict__ inputs,  // [B, L, 3]
    const float* __restrict__ z,       // [B, L, 32]
    const float* __restrict__ W)       // [L, 35, 512]
{
    const int bq = blockIdx.x;
    const int l  = blockIdx.y;
    const int t  = threadIdx.x;

    __shared__ __align__(16) float xsf[32][36];

    for (int idx = t; idx < 32 * 36; idx += 256) {
        int bl = idx / 36, i = idx - bl * 36;
        int b = bq * 32 + bl;
        float v = 0.f;
        if (i < 3)       v = inputs[(b * Lsz + l) * 3 + i];
        else if (i < 35) v = z[(b * Lsz + l) * 32 + (i - 3)];
        xsf[bl][i] = v;
    }

    u64 w0[18], w1[18];
    const float* Wl = W + (size_t)l * Isz * Hsz;
#pragma unroll
    for (int q = 0; q < 17; q++) {
        w0[q] = pack2(Wl[(2 * q) * Hsz + t],       Wl[(2 * q + 1) * Hsz + t]);
        w1[q] = pack2(Wl[(2 * q) * Hsz + t + 256], Wl[(2 * q + 1) * Hsz + t + 256]);
    }
    w0[17] = pack2(Wl[34 * Hsz + t], 0.f);
    w1[17] = pack2(Wl[34 * Hsz + t + 256], 0.f);
    __syncthreads();

    float* crow = &g_c[((size_t)l * Bsz + bq * 32) * Hsz];
    for (int bl = 0; bl < 32; bl++) {
        u64 a0 = 0ULL, b0 = 0ULL, a1 = 0ULL, b1 = 0ULL;
#pragma unroll
        for (int Q = 0; Q < 9; Q++) {
            ulonglong2 xv = *reinterpret_cast<const ulonglong2*>(&xsf[bl][4 * Q]);
            a0 = fma2(xv.x, w0[2 * Q],     a0);
            b0 = fma2(xv.y, w0[2 * Q + 1], b0);
            a1 = fma2(xv.x, w1[2 * Q],     a1);
            b1 = fma2(xv.y, w1[2 * Q + 1], b1);
        }
        float p, q, r, s;
        unpack2(a0, p, q); unpack2(b0, r, s);
        crow[(size_t)bl * Hsz + t] = (p + q) + (r + s);
        unpack2(a1, p, q); unpack2(b1, r, s);
        crow[(size_t)bl * Hsz + t + 256] = (p + q) + (r + s);
    }
}

// ============================================================
// Kernel 2: scan (R11 float2 in-place) + tf32 RNA pre-round of h.
// dec's A operands then feed mma directly with no conversion.
// ============================================================
__global__ void __launch_bounds__(128) scan_kernel(
    const float* __restrict__ benc)    // [1, 512]
{
    const int g = blockIdx.x * 128 + threadIdx.x;   // 0..65535
    const int b = g >> 8;
    const int hp = g & 255;

    float2 be = *reinterpret_cast<const float2*>(&benc[2 * hp]);
    float2* p = reinterpret_cast<float2*>(g_c) + ((size_t)b * Hsz) / 2 + hp;
    const size_t stride = (size_t)Bsz * Hsz / 2;

    float ax = 0.f, ay = 0.f;
#pragma unroll 4
    for (int l = 0; l < Lsz; l++) {
        float2 v = p[l * stride];
        float2 o;
        o.x = __uint_as_float(to_tf32(fmaxf(ax + be.x, 0.f)));
        o.y = __uint_as_float(to_tf32(fmaxf(ay + be.y, 0.f)));
        p[l * stride] = o;
        ax += v.x; ay += v.y;
    }
}

// ============================================================
// Kernel 3: TF32 single-product decoder.
// D[128b, 40o] = h[128,512] @ V[512,40]^T, tf32 in / fp32 accum.
// R13 pipeline skeleton: 16 chunks of k=32; h double-buffered via
// cp.async (pre-rounded in scan); V register-prefetched + cvt at LDV.
// Warp w: rows 32w..32w+31 (2 m16 tiles) x 5 n8 tiles; 4 k8 steps/chunk.
// grid (bq=2, l=500), block 128. Dynamic smem 47104 B (4 CTAs/SM).
// ============================================================
__global__ void __launch_bounds__(128, 4) dec_tf32_kernel(
    const float* __restrict__ Vmu,   // [L, 512, 15]
    const float* __restrict__ bmu,   // [L, 1, 15]
    const float* __restrict__ Vsig,  // [L, 512, 15]
    const float* __restrict__ bsig,  // [L, 1, 15]
    const float* __restrict__ Vpi,   // [L, 512, 5]
    const float* __restrict__ bpi,   // [L, 1, 5]
    float* __restrict__ out)         // [B, L, 35]
{
    const int bq = blockIdx.x;
    const int l  = blockIdx.y;
    const int t  = threadIdx.x;
    const int wid = t >> 5, lane = t & 31;
    const int gr = lane >> 2, t4 = lane & 3;

    extern __shared__ float dsm[];
    float* hs = dsm;                  // [2][128][36] (32 k + 4 pad)
    float* vs = dsm + 9216;           // [2][32][40]
#define HSf(bf, row, c) hs[(bf) * 4608 + (row) * 36 + (c)]
#define VSf(bf, kk, o)  vs[(bf) * 1280 + (kk) * 40 + (o)]

    // zero V pad cols (o 35..39) once
    for (int e = t; e < 320; e += 128) {
        int bf = e / 160, r = e - bf * 160;
        VSf(bf, r / 5, 35 + r % 5) = 0.f;
    }

    // ---- V prefetch bookkeeping: 560 k-pair entries/chunk, 5/thread ----
    const float* vptr[5];
    int vkkp[5], vo[5], vrow[5];
    bool vp[5];
#pragma unroll
    for (int j = 0; j < 5; j++) {
        int e = t + 128 * j;
        vp[j] = (e < 16 * 35);
        int kk = vp[j] ? e / 35 : 0;
        int o  = vp[j] ? e - kk * 35 : 0;
        vkkp[j] = kk; vo[j] = o;
        if (o < 15)      { vptr[j] = Vmu  + ((size_t)l * Hsz + 2 * kk) * 15 + o;        vrow[j] = 15; }
        else if (o < 30) { vptr[j] = Vsig + ((size_t)l * Hsz + 2 * kk) * 15 + (o - 15); vrow[j] = 15; }
        else             { vptr[j] = Vpi  + ((size_t)l * Hsz + 2 * kk) * 5  + (o - 30); vrow[j] = 5;  }
    }
    uint32_t v0h[5], v1h[5];
#define LDV()                                                          \
    do {                                                               \
        _Pragma("unroll")                                              \
        for (int j = 0; j < 5; j++)                                    \
            if (vp[j]) {                                               \
                v0h[j] = to_tf32(vptr[j][0]);                          \
                v1h[j] = to_tf32(vptr[j][vrow[j]]);                    \
                vptr[j] += 32 * vrow[j];                               \
            }                                                          \
    } while (0)
#define STV(bf)                                                        \
    do {                                                               \
        _Pragma("unroll")                                              \
        for (int j = 0; j < 5; j++)                                    \
            if (vp[j]) {                                               \
                VSf(bf, 2 * vkkp[j],     vo[j]) = __uint_as_float(v0h[j]); \
                VSf(bf, 2 * vkkp[j] + 1, vo[j]) = __uint_as_float(v1h[j]); \
            }                                                          \
    } while (0)

    const float* hbase = g_c + ((size_t)l * Bsz + bq * 128) * Hsz;
#define CPH(tile, bf)                                                      \
    do {                                                                   \
        _Pragma("unroll")                                                  \
        for (int n = 0; n < 8; n++) {                                      \
            int idx_ = t + 128 * n;                                        \
            int row_ = idx_ >> 3, ch_ = idx_ & 7;                          \
            cp_async16(smem_u32(&HSf(bf, row_, ch_ * 4)),                  \
                       hbase + (size_t)row_ * Hsz + (tile) * 32 + ch_ * 4);\
        }                                                                  \
        cp_commit();                                                       \
    } while (0)

    // bias for this thread's columns (fragment cols 2*t4, 2*t4+1 per n8)
    float bias0[5], bias1[5];
#pragma unroll
    for (int nt = 0; nt < 5; nt++) {
#pragma unroll
        for (int s = 0; s < 2; s++) {
            int o = 8 * nt + 2 * t4 + s;
            float bv = (o < 15) ? bmu[l * 15 + o]
                     : (o < 30) ? bsig[l * 15 + (o - 15)]
                     : (o < 35) ? bpi[l * 5 + (o - 30)] : 0.f;
            if (s == 0) bias0[nt] = bv; else bias1[nt] = bv;
        }
    }

    // ---- prolog ----
    LDV();
    STV(0);
    LDV();
    CPH(0, 0);
    CPH(1, 1);

    float d[2][5][4];
#pragma unroll
    for (int mt = 0; mt < 2; mt++)
#pragma unroll
        for (int nt = 0; nt < 5; nt++)
#pragma unroll
            for (int k = 0; k < 4; k++) d[mt][nt][k] = 0.f;

    for (int tl = 0; tl < 16; tl++) {
        if (tl < 15) cp_wait<1>(); else cp_wait<0>();
        __syncthreads();
        if (tl < 15) STV((tl + 1) & 1);
        if (tl < 14) LDV();

        const int buf = tl & 1;
#pragma unroll
        for (int s = 0; s < 4; s++) {          // four k8 steps per chunk
            const int kb = 8 * s;
            uint32_t a[2][4];
#pragma unroll
            for (int mt = 0; mt < 2; mt++) {
                int r0 = 32 * wid + 16 * mt + gr;
                a[mt][0] = __float_as_uint(HSf(buf, r0,     kb + t4));
                a[mt][1] = __float_as_uint(HSf(buf, r0 + 8, kb + t4));
                a[mt][2] = __float_as_uint(HSf(buf, r0,     kb + 4 + t4));
                a[mt][3] = __float_as_uint(HSf(buf, r0 + 8, kb + 4 + t4));
            }
            uint32_t bfr[5][2];
#pragma unroll
            for (int nt = 0; nt < 5; nt++) {
                int o = 8 * nt + gr;
                bfr[nt][0] = __float_as_uint(VSf(buf, kb + t4,     o));
                bfr[nt][1] = __float_as_uint(VSf(buf, kb + 4 + t4, o));
            }
#pragma unroll
            for (int mt = 0; mt < 2; mt++)
#pragma unroll
                for (int nt = 0; nt < 5; nt++)
                    mma_tf32(d[mt][nt], a[mt], bfr[nt]);
        }
        __syncthreads();
        if (tl < 14) CPH(tl + 2, buf);
    }

    // ---- epilogue: fragment scatter + bias ----
#pragma unroll
    for (int mt = 0; mt < 2; mt++) {
        int b0 = bq * 128 + 32 * wid + 16 * mt + gr;
        float* o0 = out + ((size_t)b0 * Lsz + l) * OUTsz;
        float* o1 = out + ((size_t)(b0 + 8) * Lsz + l) * OUTsz;
#pragma unroll
        for (int nt = 0; nt < 5; nt++) {
            int c0 = 8 * nt + 2 * t4;
            if (c0 < OUTsz) {
                o0[c0] = d[mt][nt][0] + bias0[nt];
                o1[c0] = d[mt][nt][2] + bias0[nt];
            }
            if (c0 + 1 < OUTsz) {
                o0[c0 + 1] = d[mt][nt][1] + bias1[nt];
                o1[c0 + 1] = d[mt][nt][3] + bias1[nt];
            }
        }
    }
#undef LDV
#undef STV
#undef CPH
#undef HSf
#undef VSf
}

extern "C" void kernel_launch(void* const* d_in, const int* in_sizes, int n_in,
                              void* d_out, int out_size) {
    (void)in_sizes; (void)n_in; (void)out_size;
    const float* inputs = (const float*)d_in[0];
    const float* z      = (const float*)d_in[1];
    const float* W_enc  = (const float*)d_in[2];
    const float* b_enc  = (const float*)d_in[3];
    const float* V_mu   = (const float*)d_in[4];
    const float* b_mu   = (const float*)d_in[5];
    const float* V_sig  = (const float*)d_in[6];
    const float* b_sig  = (const float*)d_in[7];
    const float* V_pi   = (const float*)d_in[8];
    const float* b_pi   = (const float*)d_in[9];
    float* out = (float*)d_out;

    enc_kernel<<<dim3(8, Lsz), 256>>>(inputs, z, W_enc);
    scan_kernel<<<(Bsz * Hsz / 2) / 128, 128>>>(b_enc);
    dec_tf32_kernel<<<dim3(2, Lsz), 128, 47104>>>(V_mu, b_mu, V_sig, b_sig,
                                                  V_pi, b_pi, out);
}